// round 14
// baseline (speedup 1.0000x reference)
#include <cuda_runtime.h>

#define N_PH  1024
#define IMG   256
#define NPIX  (IMG * IMG)
#define TW    16          // tile width  (pixels)
#define TH    8           // tile height (pixels)
#define TPIX  (TW * TH)   // 128 pixels per tile
#define CAPC  256         // clamped-sigma survivors (foveal; analysis bound ~130)
#define CAPG  128         // general survivors (peripheral; analysis bound ~60)

// Constants from the reference
#define C_SPREAD_INV  (1.0f / 0.000675f)
#define C_R2S         0.5f
#define C_SLOPE       19152642.5f
#define C_HALF        1.057e-07f
#define C_RHEO        2.39e-05f
#define C_PWF         (0.00017f * 300.0f)
#define C_ISCALE      8e-05f
#define HALF_LOG2E    0.72134752f    // log2(e)/2 ; exp(-d2/2s2) = exp2(-HALF_LOG2E*d2/s2)
#define SQRT_HL2E     0.84932184f    // sqrt(HALF_LOG2E): pre-scales coords for clamped list

// Per-phosphene precomputed parameters (rewritten by prep_kernel every replay).
__device__ float4 g_A[N_PH];   // cxs, cys, rad2 (5-sigma, px^2 units), class (1=clamped)
__device__ float4 g_B[N_PH];   // Bw0, Bw1, m0, m1

// Single-instruction exp2 (MUFU.EX2), independent of compiler fast-math flags.
__device__ __forceinline__ float ex2_approx(float x) {
    float r;
    asm("ex2.approx.f32 %0, %1;" : "=f"(r) : "f"(x));
    return r;
}

// ---- Prologue: per-phosphene parameters, computed ONCE instead of per-tile ----
__global__ void __launch_bounds__(256)
prep_kernel(const float* __restrict__ stim,
            const float* __restrict__ vx,
            const float* __restrict__ vy,
            const float* __restrict__ Marr,
            const float* __restrict__ px,
            const int*   __restrict__ idx)
{
    const int n = blockIdx.x * 256 + threadIdx.x;   // 4 blocks x 256 = 1024

    // Speculative identity loads in parallel with the idx load; gather
    // fallback (never taken when idx is arange, as here) keeps correctness.
    float s0 = stim[n];
    float s1 = stim[N_PH + n];
    const int e = idx[n];
    if (e != n) { s0 = stim[e]; s1 = stim[N_PH + e]; }

    const float fov = px[NPIX - 1];
    const float d2p = (float)IMG / (2.0f * fov);    // deg2pix
    const float qk  = C_ISCALE * C_SPREAD_INV * (C_R2S * d2p) * (C_R2S * d2p);

    const float cxs = vx[n] * d2p;
    const float cys = vy[n] * d2p;
    const float Mv  = Marr[n];
    const float M2  = Mv * Mv;
    const float qM    = fmaxf(s0, s1) * qk;
    const float sdenM = fmaxf(qM, M2);              // max sigma^2 * M2 across batches

    // 5-sigma footprint radius^2 in pixel units (dropped terms <= 7e-6 each,
    // worst-pixel total ~2e-4, threshold 1e-3).
    const float rad2 = 25.0f * __fdividef(sdenM, M2);

    // Brightness weights (x2 output scale folded in)
    const float t0  = C_SLOPE * (fmaxf(s0 * C_ISCALE - C_RHEO, 0.0f) * C_PWF - C_HALF);
    const float t1  = C_SLOPE * (fmaxf(s1 * C_ISCALE - C_RHEO, 0.0f) * C_PWF - C_HALF);
    const float Bw0 = __fdividef(2.0f, 1.0f + __expf(-t0));
    const float Bw1 = __fdividef(2.0f, 1.0f + __expf(-t1));

    const float m0 = -HALF_LOG2E * __fdividef(M2, fmaxf(s0 * qk, M2));
    const float m1 = -HALF_LOG2E * __fdividef(M2, fmaxf(s1 * qk, M2));
    const float cls = (qM <= M2) ? 1.0f : 0.0f;     // both batches sigma-clamped

    g_A[n] = make_float4(cxs, cys, rad2, cls);
    g_B[n] = make_float4(Bw0, Bw1, m0, m1);
}

// ---- Main: cull + render per 16x8 tile ----
__global__ void __launch_bounds__(256)
fused_kernel(const float* __restrict__ px,
             const float* __restrict__ py,
             float*       __restrict__ out)
{
    __shared__ float4 shC[CAPC];    // clamped: cxs*S, cys*S, Bw0, Bw1
    __shared__ float4 shG[CAPG];    // general: cxs, cys, m0, m1
    __shared__ float2 shGb[CAPG];   // general: Bw0, Bw1
    __shared__ float2 red[TPIX];    // partial sums from upper thread-half
    __shared__ int    cntc, cntg;

    const int tid  = threadIdx.x;
    const int tile = blockIdx.x;            // 0..511 : 16 x-tiles * 32 y-tiles
    const int tx0  = (tile & 15) * TW;
    const int ty0  = (tile >> 4) * TH;

    if (tid == 0) { cntc = 0; cntg = 0; }

    // fov = px.max() = last element of ascending linspace
    const float fov = px[NPIX - 1];
    const float d2p = (float)IMG / (2.0f * fov);   // deg2pix

    // Scaled pixel coordinate of column w: px[w]*d2p == w*(256/255) - 128 (±ulp).
    // Approximation error (~1e-3 px) is absorbed by the 5-sigma footprint.
    const float PSTEP = 256.0f / 255.0f;
    const float bxlo = tx0 * PSTEP - 128.0f;
    const float bxhi = (tx0 + TW - 1) * PSTEP - 128.0f;
    const float bylo = ty0 * PSTEP - 128.0f;
    const float byhi = (ty0 + TH - 1) * PSTEP - 128.0f;

    __syncthreads();   // counters visible

    // ---- Phase 1: slim cull over precomputed per-phosphene params ----
    #pragma unroll
    for (int it = 0; it < N_PH / 256; it++) {
        const int n = it * 256 + tid;
        const float4 A = g_A[n];            // coalesced LDG.128, L2-hot
        const float4 B = g_B[n];            // issued up front, consumed on pass

        const float ddx = fmaxf(fmaxf(bxlo - A.x, A.x - bxhi), 0.0f);
        const float ddy = fmaxf(fmaxf(bylo - A.y, A.y - byhi), 0.0f);
        const float dd2 = fmaf(ddx, ddx, ddy * ddy);
        if (dd2 > A.z) continue;

        if (A.w != 0.0f) {
            const int p = atomicAdd(&cntc, 1);
            if (p < CAPC)
                shC[p] = make_float4(A.x * SQRT_HL2E, A.y * SQRT_HL2E, B.x, B.y);
        } else {
            const int p = atomicAdd(&cntg, 1);
            if (p < CAPG) {
                shG[p]  = make_float4(A.x, A.y, B.z, B.w);
                shGb[p] = make_float2(B.x, B.y);
            }
        }
    }
    __syncthreads();

    // ---- Phase 2: 128 pixels, survivor lists split across the two thread halves ----
    const int pl  = tid & (TPIX - 1);        // pixel index within tile
    const int w   = tx0 + (pl & 15);
    const int h   = ty0 + (pl >> 4);
    // Exact grid values (match reference bit-level coordinates):
    // px[y][x] depends only on x (row 0); py[y][x] only on y (col 0).
    const float pxs = px[w] * d2p;
    const float pys = py[h * IMG] * d2p;
    const float pxq = pxs * SQRT_HL2E;       // pre-scaled for the clamped list
    const float pyq = pys * SQRT_HL2E;

    const int nc = min(cntc, CAPC);
    const int ng = min(cntg, CAPG);
    const bool lowhalf = (tid < TPIX);
    const int c_lo = lowhalf ? 0 : (nc >> 1);
    const int c_hi = lowhalf ? (nc >> 1) : nc;
    const int g_lo = lowhalf ? 0 : (ng >> 1);
    const int g_hi = lowhalf ? (ng >> 1) : ng;

    float acc0 = 0.0f, acc1 = 0.0f;

    // Clamped list: one EX2 serves both batches.
    #pragma unroll 4
    for (int i = c_lo; i < c_hi; i++) {
        const float4 a = shC[i];
        const float dx = pxq - a.x;
        const float dy = pyq - a.y;
        const float d2n = fmaf(dx, -dx, -(dy * dy));  // = -HALF_LOG2E * dist2
        const float g = ex2_approx(d2n);
        acc0 = fmaf(a.z, g, acc0);
        acc1 = fmaf(a.w, g, acc1);
    }

    // General list: two exps (distinct sigmas per batch).
    #pragma unroll 2
    for (int i = g_lo; i < g_hi; i++) {
        const float4 a  = shG[i];
        const float2 bw = shGb[i];
        const float dx = pxs - a.x;
        const float dy = pys - a.y;
        const float d2 = fmaf(dx, dx, dy * dy);
        acc0 = fmaf(bw.x, ex2_approx(d2 * a.z), acc0);
        acc1 = fmaf(bw.y, ex2_approx(d2 * a.w), acc1);
    }

    if (!lowhalf) red[pl] = make_float2(acc0, acc1);
    __syncthreads();

    if (lowhalf) {
        const float2 r = red[pl];
        const int pix = h * IMG + w;
        out[pix]        = fminf(acc0 + r.x, 1.0f);   // acc >= 0 always
        out[NPIX + pix] = fminf(acc1 + r.y, 1.0f);
    }
}

extern "C" void kernel_launch(void* const* d_in, const int* in_sizes, int n_in,
                              void* d_out, int out_size)
{
    const float* stim = (const float*)d_in[0];   // [2,32,32]
    const float* vx   = (const float*)d_in[1];   // [1024]
    const float* vy   = (const float*)d_in[2];   // [1024]
    const float* M    = (const float*)d_in[3];   // [1024]
    const float* px   = (const float*)d_in[4];   // [256,256]
    const float* py   = (const float*)d_in[5];   // [256,256]
    const int*   idx  = (const int*)  d_in[6];   // [1024]
    float* out = (float*)d_out;                  // [2,1,256,256]

    prep_kernel<<<N_PH / 256, 256>>>(stim, vx, vy, M, px, idx);
    fused_kernel<<<(IMG / TW) * (IMG / TH), 256>>>(px, py, out);
}

// round 15
// speedup vs baseline: 1.1527x; 1.1527x over previous
#include <cuda_runtime.h>

#define N_PH  1024
#define IMG   256
#define NPIX  (IMG * IMG)
#define TW    16          // tile width  (pixels)
#define TH    16          // tile height (pixels)
#define TPIX  (TW * TH)   // 256 pixels per tile
#define NTHR  512         // threads per block (2 halves of 256)
#define CAPC  384         // clamped-sigma survivors (foveal; analysis bound ~240)
#define CAPG  160         // general survivors (peripheral; analysis bound ~80)

// Constants from the reference
#define C_SPREAD_INV  (1.0f / 0.000675f)
#define C_R2S         0.5f
#define C_SLOPE       19152642.5f
#define C_HALF        1.057e-07f
#define C_RHEO        2.39e-05f
#define C_PWF         (0.00017f * 300.0f)
#define C_ISCALE      8e-05f
#define LOG2E         1.44269504f
#define HALF_LOG2E    0.72134752f    // log2(e)/2 ; exp(-d2/2s2) = exp2(-HALF_LOG2E*d2/s2)
#define SQRT_HL2E     0.84932184f    // sqrt(HALF_LOG2E): pre-scales coords for clamped list

// Single-instruction MUFU ops, independent of compiler fast-math flags.
__device__ __forceinline__ float ex2_approx(float x) {
    float r; asm("ex2.approx.f32 %0, %1;" : "=f"(r) : "f"(x)); return r;
}
__device__ __forceinline__ float rcp_approx(float x) {
    float r; asm("rcp.approx.f32 %0, %1;" : "=f"(r) : "f"(x)); return r;
}

__global__ void __launch_bounds__(NTHR)
fused_kernel(const float* __restrict__ stim,
             const float* __restrict__ vx,
             const float* __restrict__ vy,
             const float* __restrict__ Marr,
             const float* __restrict__ px,
             const float* __restrict__ py,
             const int*   __restrict__ idx,
             float*       __restrict__ out)
{
    __shared__ float4 shC[CAPC];    // clamped: cxs*S, cys*S, Bw0, Bw1
    __shared__ float4 shG[CAPG];    // general: cxs, cys, m0, m1
    __shared__ float2 shGb[CAPG];   // general: Bw0, Bw1
    __shared__ float2 red[TPIX];    // partial sums from upper thread-half
    __shared__ int    cntc, cntg;

    const int tid  = threadIdx.x;
    const int tile = blockIdx.x;            // 0..255 : 16 x-tiles * 16 y-tiles
    const int tx0  = (tile & 15) * TW;
    const int ty0  = (tile >> 4) * TH;

    if (tid == 0) { cntc = 0; cntg = 0; }

    // fov = px.max() = last element of ascending linspace
    const float fov = px[NPIX - 1];
    const float d2p = (float)IMG / (2.0f * fov);   // deg2pix

    // Scaled pixel coordinate of column w: px[w]*d2p == w*(256/255) - 128 (±ulp).
    // Approximation error (~1e-3 px) is absorbed by the 5-sigma footprint.
    const float PSTEP = 256.0f / 255.0f;
    const float bxlo = tx0 * PSTEP - 128.0f;
    const float bxhi = (tx0 + TW - 1) * PSTEP - 128.0f;
    const float bylo = ty0 * PSTEP - 128.0f;
    const float byhi = (ty0 + TH - 1) * PSTEP - 128.0f;

    // q = s*qk equals sigma_px^2 * M^2 before the >=1 clamp
    const float qk = C_ISCALE * C_SPREAD_INV * (C_R2S * d2p) * (C_R2S * d2p);

    __syncthreads();   // counters visible

    // ---- Phase 1: one scan over the 1024 phosphenes for BOTH batches ----
    // Division/sqrt-free cull; MUFU-only transcendentals on the survivor path.
    #pragma unroll
    for (int it = 0; it < N_PH / NTHR; it++) {
        const int n = it * NTHR + tid;
        // Speculative identity loads run in parallel with the idx load; the
        // gather fallback (never taken when idx is arange, as here) keeps
        // correctness for any idx.
        float s0 = stim[n];                    // batch 0
        float s1 = stim[N_PH + n];             // batch 1
        const int e = idx[n];
        if (e != n) { s0 = stim[e]; s1 = stim[N_PH + e]; }

        const float cxs = vx[n] * d2p;
        const float cys = vy[n] * d2p;
        const float Mv  = Marr[n];
        const float M2  = Mv * Mv;
        const float qM    = fmaxf(s0, s1) * qk;
        const float sdenM = fmaxf(qM, M2);     // max sigma^2 * M2 across batches

        // 5-sigma footprint on the larger sigma (dropped terms <= 7e-6 each,
        // worst-pixel total ~2e-4, threshold 1e-3):
        // dd2 > 25*sigma^2  <=>  dd2*M2 > 25*max(q, M2)
        const float ddx = fmaxf(fmaxf(bxlo - cxs, cxs - bxhi), 0.0f);
        const float ddy = fmaxf(fmaxf(bylo - cys, cys - byhi), 0.0f);
        const float dd2 = fmaf(ddx, ddx, ddy * ddy);
        if (dd2 * M2 > 25.0f * sdenM) continue;

        // Survivor-only transcendentals, MUFU-only (x2 output scale folded in):
        // Bw = 2 / (1 + exp(-t)) = 2 * rcp(1 + ex2(-t*log2e))
        const float t0  = C_SLOPE * (fmaxf(s0 * C_ISCALE - C_RHEO, 0.0f) * C_PWF - C_HALF);
        const float t1  = C_SLOPE * (fmaxf(s1 * C_ISCALE - C_RHEO, 0.0f) * C_PWF - C_HALF);
        const float Bw0 = 2.0f * rcp_approx(1.0f + ex2_approx(t0 * -LOG2E));
        const float Bw1 = 2.0f * rcp_approx(1.0f + ex2_approx(t1 * -LOG2E));

        if (qM <= M2) {
            // Both batches sigma-clamped (all foveal survivors): m0 = m1 =
            // -HALF_LOG2E. One shared exp in phase 2; fold the constant into
            // the coordinates now.
            const int p = atomicAdd(&cntc, 1);
            if (p < CAPC)
                shC[p] = make_float4(cxs * SQRT_HL2E, cys * SQRT_HL2E, Bw0, Bw1);
        } else {
            const float m0 = (-HALF_LOG2E) * M2 * rcp_approx(fmaxf(s0 * qk, M2));
            const float m1 = (-HALF_LOG2E) * M2 * rcp_approx(fmaxf(s1 * qk, M2));
            const int p = atomicAdd(&cntg, 1);
            if (p < CAPG) {
                shG[p]  = make_float4(cxs, cys, m0, m1);
                shGb[p] = make_float2(Bw0, Bw1);
            }
        }
    }
    __syncthreads();

    // ---- Phase 2: 256 pixels, survivor lists split across the two thread halves ----
    const int pl  = tid & (TPIX - 1);        // pixel index within tile
    const int w   = tx0 + (pl & 15);
    const int h   = ty0 + (pl >> 4);
    // Exact grid values (match reference bit-level coordinates):
    // px[y][x] depends only on x (row 0); py[y][x] only on y (col 0).
    const float pxs = px[w] * d2p;
    const float pys = py[h * IMG] * d2p;
    const float pxq = pxs * SQRT_HL2E;       // pre-scaled for the clamped list
    const float pyq = pys * SQRT_HL2E;

    const int nc = min(cntc, CAPC);
    const int ng = min(cntg, CAPG);
    const bool lowhalf = (tid < TPIX);
    const int c_lo = lowhalf ? 0 : (nc >> 1);
    const int c_hi = lowhalf ? (nc >> 1) : nc;
    const int g_lo = lowhalf ? 0 : (ng >> 1);
    const int g_hi = lowhalf ? (ng >> 1) : ng;

    float acc0 = 0.0f, acc1 = 0.0f;

    // Clamped list: one EX2 serves both batches.
    #pragma unroll 4
    for (int i = c_lo; i < c_hi; i++) {
        const float4 a = shC[i];
        const float dx = pxq - a.x;
        const float dy = pyq - a.y;
        const float d2n = fmaf(dx, -dx, -(dy * dy));  // = -HALF_LOG2E * dist2
        const float g = ex2_approx(d2n);
        acc0 = fmaf(a.z, g, acc0);
        acc1 = fmaf(a.w, g, acc1);
    }

    // General list: two exps (distinct sigmas per batch).
    #pragma unroll 2
    for (int i = g_lo; i < g_hi; i++) {
        const float4 a  = shG[i];
        const float2 bw = shGb[i];
        const float dx = pxs - a.x;
        const float dy = pys - a.y;
        const float d2 = fmaf(dx, dx, dy * dy);
        acc0 = fmaf(bw.x, ex2_approx(d2 * a.z), acc0);
        acc1 = fmaf(bw.y, ex2_approx(d2 * a.w), acc1);
    }

    if (!lowhalf) red[pl] = make_float2(acc0, acc1);
    __syncthreads();

    if (lowhalf) {
        const float2 r = red[pl];
        const int pix = h * IMG + w;
        out[pix]        = fminf(acc0 + r.x, 1.0f);   // acc >= 0 always
        out[NPIX + pix] = fminf(acc1 + r.y, 1.0f);
    }
}

extern "C" void kernel_launch(void* const* d_in, const int* in_sizes, int n_in,
                              void* d_out, int out_size)
{
    const float* stim = (const float*)d_in[0];   // [2,32,32]
    const float* vx   = (const float*)d_in[1];   // [1024]
    const float* vy   = (const float*)d_in[2];   // [1024]
    const float* M    = (const float*)d_in[3];   // [1024]
    const float* px   = (const float*)d_in[4];   // [256,256]
    const float* py   = (const float*)d_in[5];   // [256,256]
    const int*   idx  = (const int*)  d_in[6];   // [1024]
    float* out = (float*)d_out;                  // [2,1,256,256]

    fused_kernel<<<(IMG / TW) * (IMG / TH), NTHR>>>(stim, vx, vy, M, px, py, idx, out);
}

// round 16
// speedup vs baseline: 1.1697x; 1.0148x over previous
#include <cuda_runtime.h>

#define N_PH  1024
#define IMG   256
#define NPIX  (IMG * IMG)
#define TW    16          // tile width  (pixels)
#define TH    8           // tile height (pixels)
#define TPIX  (TW * TH)   // 128 pixels per tile
#define CAPC  256         // clamped-sigma survivors (foveal; analysis bound ~130)
#define CAPG  128         // general survivors (peripheral; analysis bound ~60)

// Constants from the reference
#define C_SPREAD_INV  (1.0f / 0.000675f)
#define C_R2S         0.5f
#define C_SLOPE       19152642.5f
#define C_HALF        1.057e-07f
#define C_RHEO        2.39e-05f
#define C_PWF         (0.00017f * 300.0f)
#define C_ISCALE      8e-05f
#define HALF_LOG2E    0.72134752f    // log2(e)/2 ; exp(-d2/2s2) = exp2(-HALF_LOG2E*d2/s2)
#define SQRT_HL2E     0.84932184f    // sqrt(HALF_LOG2E): pre-scales coords ("q units")

// Single-instruction MUFU ops, independent of compiler fast-math flags.
__device__ __forceinline__ float ex2_approx(float x) {
    float r; asm("ex2.approx.f32 %0, %1;" : "=f"(r) : "f"(x)); return r;
}
__device__ __forceinline__ float lg2_approx(float x) {
    float r; asm("lg2.approx.f32 %0, %1;" : "=f"(r) : "f"(x)); return r;
}

__global__ void __launch_bounds__(256)
fused_kernel(const float* __restrict__ stim,
             const float* __restrict__ vx,
             const float* __restrict__ vy,
             const float* __restrict__ Marr,
             const float* __restrict__ px,
             const float* __restrict__ py,
             const int*   __restrict__ idx,
             float*       __restrict__ out)
{
    __shared__ float4 shC[CAPC];    // clamped: 2cx', 2cy', lg2(Bw0)-|c'|^2, Bw1/Bw0
    __shared__ float4 shG[CAPG];    // general: cxs, cys, m0, m1
    __shared__ float2 shGb[CAPG];   // general: Bw0, Bw1
    __shared__ float2 red[TPIX];    // partial sums from upper thread-half
    __shared__ int    cntc, cntg;

    const int tid  = threadIdx.x;
    const int tile = blockIdx.x;            // 0..511 : 16 x-tiles * 32 y-tiles
    const int tx0  = (tile & 15) * TW;
    const int ty0  = (tile >> 4) * TH;

    if (tid == 0) { cntc = 0; cntg = 0; }

    // fov = px.max() = last element of ascending linspace
    const float fov = px[NPIX - 1];
    const float d2p = (float)IMG / (2.0f * fov);   // deg2pix

    // Scaled pixel coordinate of column w: px[w]*d2p == w*(256/255) - 128 (±ulp).
    // Approximation error (~1e-3 px) is absorbed by the 4.47-sigma footprint.
    const float PSTEP = 256.0f / 255.0f;
    const float bxlo = tx0 * PSTEP - 128.0f;
    const float bxhi = (tx0 + TW - 1) * PSTEP - 128.0f;
    const float bylo = ty0 * PSTEP - 128.0f;
    const float byhi = (ty0 + TH - 1) * PSTEP - 128.0f;

    // Tile center in q units: origin for the clamped linear exponent form
    // (keeps all exponents within ~±300, no overflow; far tails flush to 0).
    const float cpx = ((tx0 + 0.5f * (TW - 1)) * PSTEP - 128.0f) * SQRT_HL2E;
    const float cpy = ((ty0 + 0.5f * (TH - 1)) * PSTEP - 128.0f) * SQRT_HL2E;

    // q = s*qk equals sigma_px^2 * M^2 before the >=1 clamp
    const float qk = C_ISCALE * C_SPREAD_INV * (C_R2S * d2p) * (C_R2S * d2p);

    __syncthreads();   // counters visible

    // ---- Phase 1: one scan over the 1024 phosphenes for BOTH batches ----
    // Division/sqrt-free cull; transcendentals only on the survivor path.
    for (int n = tid; n < N_PH; n += 256) {
        // Speculative identity loads run in parallel with the idx load; the
        // gather fallback (never taken when idx is arange, as here) keeps
        // correctness for any idx.
        float s0 = stim[n];                    // batch 0
        float s1 = stim[N_PH + n];             // batch 1
        const int e = idx[n];
        if (e != n) { s0 = stim[e]; s1 = stim[N_PH + e]; }

        const float cxs = vx[n] * d2p;
        const float cys = vy[n] * d2p;
        const float Mv  = Marr[n];
        const float M2  = Mv * Mv;
        const float qM    = fmaxf(s0, s1) * qk;
        const float sdenM = fmaxf(qM, M2);     // max sigma^2 * M2 across batches

        // 4.47-sigma footprint on the larger sigma (dropped terms <= 4.5e-5
        // each; empirically the cut radius barely moves rel_err — observed
        // 1.1e-6 -> 1.3e-6 going 8.4σ -> 5σ; threshold 1e-3):
        // dd2 > 20*sigma^2  <=>  dd2*M2 > 20*max(q, M2)
        const float ddx = fmaxf(fmaxf(bxlo - cxs, cxs - bxhi), 0.0f);
        const float ddy = fmaxf(fmaxf(bylo - cys, cys - byhi), 0.0f);
        const float dd2 = fmaf(ddx, ddx, ddy * ddy);
        if (dd2 * M2 > 20.0f * sdenM) continue;

        // Survivor-only transcendentals (brightness weights, x2 scale folded in)
        const float t0  = C_SLOPE * (fmaxf(s0 * C_ISCALE - C_RHEO, 0.0f) * C_PWF - C_HALF);
        const float t1  = C_SLOPE * (fmaxf(s1 * C_ISCALE - C_RHEO, 0.0f) * C_PWF - C_HALF);
        const float Bw0 = __fdividef(2.0f, 1.0f + __expf(-t0));
        const float Bw1 = __fdividef(2.0f, 1.0f + __expf(-t1));

        if (qM <= M2) {
            // Both batches sigma-clamped (all foveal survivors): shared
            // exponent. Store the tile-centered LINEAR form:
            //   exponent(pixel) = (2cx')*px' + (2cy')*py' + cc + pp
            // with pp = -(px'^2+py'^2) factored out per pixel and Bw0 folded
            // in via +lg2(Bw0); batch 1 recovered by the ratio Bw1/Bw0.
            const float cxq = fmaf(cxs, SQRT_HL2E, -cpx);
            const float cyq = fmaf(cys, SQRT_HL2E, -cpy);
            const float cc  = lg2_approx(Bw0) - fmaf(cxq, cxq, cyq * cyq);
            const float r   = __fdividef(Bw1, Bw0);
            const int p = atomicAdd(&cntc, 1);
            if (p < CAPC)
                shC[p] = make_float4(2.0f * cxq, 2.0f * cyq, cc, r);
        } else {
            const float m0 = -HALF_LOG2E * __fdividef(M2, fmaxf(s0 * qk, M2));
            const float m1 = -HALF_LOG2E * __fdividef(M2, fmaxf(s1 * qk, M2));
            const int p = atomicAdd(&cntg, 1);
            if (p < CAPG) {
                shG[p]  = make_float4(cxs, cys, m0, m1);
                shGb[p] = make_float2(Bw0, Bw1);
            }
        }
    }
    __syncthreads();

    // ---- Phase 2: 128 pixels, survivor lists split across the two thread halves ----
    const int pl  = tid & (TPIX - 1);        // pixel index within tile
    const int w   = tx0 + (pl & 15);
    const int h   = ty0 + (pl >> 4);
    // Exact grid values (match reference bit-level coordinates):
    // px[y][x] depends only on x (row 0); py[y][x] only on y (col 0).
    const float pxs = px[w] * d2p;
    const float pys = py[h * IMG] * d2p;
    const float pxq = fmaf(pxs, SQRT_HL2E, -cpx);   // tile-centered q units
    const float pyq = fmaf(pys, SQRT_HL2E, -cpy);
    const float pp  = -fmaf(pxq, pxq, pyq * pyq);
    const float K   = ex2_approx(pp);               // factored out of clamped sum

    const int nc = min(cntc, CAPC);
    const int ng = min(cntg, CAPG);
    const bool lowhalf = (tid < TPIX);
    const int c_lo = lowhalf ? 0 : (nc >> 1);
    const int c_hi = lowhalf ? (nc >> 1) : nc;
    const int g_lo = lowhalf ? 0 : (ng >> 1);
    const int g_hi = lowhalf ? (ng >> 1) : ng;

    float accc0 = 0.0f, accc1 = 0.0f;   // clamped partials (x K pending)
    float acc0  = 0.0f, acc1  = 0.0f;   // general sums

    // Clamped list: linear exponent, one EX2 serves both batches.
    #pragma unroll 4
    for (int i = c_lo; i < c_hi; i++) {
        const float4 a = shC[i];
        const float v = fmaf(a.x, pxq, fmaf(a.y, pyq, a.z));
        const float g = ex2_approx(v);           // = Bw0 * gauss / K
        accc0 += g;
        accc1 = fmaf(a.w, g, accc1);
    }

    // General list: two exps (distinct sigmas per batch).
    #pragma unroll 2
    for (int i = g_lo; i < g_hi; i++) {
        const float4 a  = shG[i];
        const float2 bw = shGb[i];
        const float dx = pxs - a.x;
        const float dy = pys - a.y;
        const float d2 = fmaf(dx, dx, dy * dy);
        acc0 = fmaf(bw.x, ex2_approx(d2 * a.z), acc0);
        acc1 = fmaf(bw.y, ex2_approx(d2 * a.w), acc1);
    }

    acc0 = fmaf(K, accc0, acc0);
    acc1 = fmaf(K, accc1, acc1);

    if (!lowhalf) red[pl] = make_float2(acc0, acc1);
    __syncthreads();

    if (lowhalf) {
        const float2 r = red[pl];
        const int pix = h * IMG + w;
        out[pix]        = fminf(acc0 + r.x, 1.0f);   // acc >= 0 always
        out[NPIX + pix] = fminf(acc1 + r.y, 1.0f);
    }
}

extern "C" void kernel_launch(void* const* d_in, const int* in_sizes, int n_in,
                              void* d_out, int out_size)
{
    const float* stim = (const float*)d_in[0];   // [2,32,32]
    const float* vx   = (const float*)d_in[1];   // [1024]
    const float* vy   = (const float*)d_in[2];   // [1024]
    const float* M    = (const float*)d_in[3];   // [1024]
    const float* px   = (const float*)d_in[4];   // [256,256]
    const float* py   = (const float*)d_in[5];   // [256,256]
    const int*   idx  = (const int*)  d_in[6];   // [1024]
    float* out = (float*)d_out;                  // [2,1,256,256]

    fused_kernel<<<(IMG / TW) * (IMG / TH), 256>>>(stim, vx, vy, M, px, py, idx, out);
}

// round 17
// speedup vs baseline: 1.2008x; 1.0265x over previous
#include <cuda_runtime.h>

#define N_PH  1024
#define IMG   256
#define NPIX  (IMG * IMG)
#define TW    16          // tile width  (pixels)
#define TH    8           // tile height (pixels)
#define NPAIR 64          // 8 x-pairs * 8 rows: each thread-slot renders 2 adjacent pixels
#define CAPC  256         // clamped-sigma survivors (foveal; analysis bound ~110 at 20σ²)
#define CAPG  128         // general survivors (peripheral; analysis bound ~50)

// Constants from the reference
#define C_SPREAD_INV  (1.0f / 0.000675f)
#define C_R2S         0.5f
#define C_SLOPE       19152642.5f
#define C_HALF        1.057e-07f
#define C_RHEO        2.39e-05f
#define C_PWF         (0.00017f * 300.0f)
#define C_ISCALE      8e-05f
#define HALF_LOG2E    0.72134752f    // log2(e)/2 ; exp(-d2/2s2) = exp2(-HALF_LOG2E*d2/s2)
#define SQRT_HL2E     0.84932184f    // sqrt(HALF_LOG2E): pre-scales coords ("q units")
#define PSTEP         (256.0f / 255.0f)          // pixel step in scaled-pixel units
#define PSTEP2        (PSTEP * PSTEP)
#define DQ            (PSTEP * SQRT_HL2E)        // pixel step in q units

// Single-instruction MUFU ops, independent of compiler fast-math flags.
__device__ __forceinline__ float ex2_approx(float x) {
    float r; asm("ex2.approx.f32 %0, %1;" : "=f"(r) : "f"(x)); return r;
}
__device__ __forceinline__ float lg2_approx(float x) {
    float r; asm("lg2.approx.f32 %0, %1;" : "=f"(r) : "f"(x)); return r;
}

__global__ void __launch_bounds__(256)
fused_kernel(const float* __restrict__ stim,
             const float* __restrict__ vx,
             const float* __restrict__ vy,
             const float* __restrict__ Marr,
             const float* __restrict__ px,
             const float* __restrict__ py,
             const int*   __restrict__ idx,
             float*       __restrict__ out)
{
    __shared__ float4 shC[CAPC];     // clamped: 2cx', 2cy', lg2(Bw0)-|c'|^2, Bw1/Bw0
    __shared__ float  shCs[CAPC];    // clamped: sx = exp2(2cx' * DQ)  (x-step factor)
    __shared__ float4 shG[CAPG];     // general: cxs, cys, m0, m1
    __shared__ float2 shGb[CAPG];    // general: Bw0, Bw1
    __shared__ float4 red[3][NPAIR]; // partial sums from survivor-groups 1..3
    __shared__ int    cntc, cntg;

    const int tid  = threadIdx.x;
    const int tile = blockIdx.x;            // 0..511 : 16 x-tiles * 32 y-tiles
    const int tx0  = (tile & 15) * TW;
    const int ty0  = (tile >> 4) * TH;

    if (tid == 0) { cntc = 0; cntg = 0; }

    // fov = px.max() = last element of ascending linspace
    const float fov = px[NPIX - 1];
    const float d2p = (float)IMG / (2.0f * fov);   // deg2pix

    // Scaled pixel coordinate of column w: px[w]*d2p == w*(256/255) - 128 (±ulp).
    // Approximation error (~2e-5 px) is absorbed by the 4.47-sigma footprint.
    const float bxlo = tx0 * PSTEP - 128.0f;
    const float bxhi = (tx0 + TW - 1) * PSTEP - 128.0f;
    const float bylo = ty0 * PSTEP - 128.0f;
    const float byhi = (ty0 + TH - 1) * PSTEP - 128.0f;

    // Tile center in q units: origin for the clamped linear exponent form
    // (keeps all exponents within ~±300, no overflow; far tails flush to 0).
    const float cpx = ((tx0 + 0.5f * (TW - 1)) * PSTEP - 128.0f) * SQRT_HL2E;
    const float cpy = ((ty0 + 0.5f * (TH - 1)) * PSTEP - 128.0f) * SQRT_HL2E;

    // q = s*qk equals sigma_px^2 * M^2 before the >=1 clamp
    const float qk = C_ISCALE * C_SPREAD_INV * (C_R2S * d2p) * (C_R2S * d2p);

    __syncthreads();   // counters visible

    // ---- Phase 1: one scan over the 1024 phosphenes for BOTH batches ----
    // Division/sqrt-free cull; transcendentals only on the survivor path.
    for (int n = tid; n < N_PH; n += 256) {
        // Speculative identity loads run in parallel with the idx load; the
        // gather fallback (never taken when idx is arange, as here) keeps
        // correctness for any idx.
        float s0 = stim[n];                    // batch 0
        float s1 = stim[N_PH + n];             // batch 1
        const int e = idx[n];
        if (e != n) { s0 = stim[e]; s1 = stim[N_PH + e]; }

        const float cxs = vx[n] * d2p;
        const float cys = vy[n] * d2p;
        const float Mv  = Marr[n];
        const float M2  = Mv * Mv;
        const float qM    = fmaxf(s0, s1) * qk;
        const float sdenM = fmaxf(qM, M2);     // max sigma^2 * M2 across batches

        // 4.47-sigma footprint on the larger sigma (validated at rel_err 8e-6):
        // dd2 > 20*sigma^2  <=>  dd2*M2 > 20*max(q, M2)
        const float ddx = fmaxf(fmaxf(bxlo - cxs, cxs - bxhi), 0.0f);
        const float ddy = fmaxf(fmaxf(bylo - cys, cys - byhi), 0.0f);
        const float dd2 = fmaf(ddx, ddx, ddy * ddy);
        if (dd2 * M2 > 20.0f * sdenM) continue;

        // Survivor-only transcendentals (brightness weights, x2 scale folded in)
        const float t0  = C_SLOPE * (fmaxf(s0 * C_ISCALE - C_RHEO, 0.0f) * C_PWF - C_HALF);
        const float t1  = C_SLOPE * (fmaxf(s1 * C_ISCALE - C_RHEO, 0.0f) * C_PWF - C_HALF);
        const float Bw0 = __fdividef(2.0f, 1.0f + __expf(-t0));
        const float Bw1 = __fdividef(2.0f, 1.0f + __expf(-t1));

        if (qM <= M2) {
            // Both batches sigma-clamped (all foveal survivors). Tile-centered
            // LINEAR exponent form: exponent(pixel) = ax*px' + ay*py' + cc + pp,
            // pp factored out per pixel, Bw0 folded in via +lg2(Bw0).
            // sx = exp2(ax*DQ): per-survivor x-step factor so one EX2 serves
            // two adjacent pixels in phase 2.
            const float cxq = fmaf(cxs, SQRT_HL2E, -cpx);
            const float cyq = fmaf(cys, SQRT_HL2E, -cpy);
            const float ax  = 2.0f * cxq;
            const float cc  = lg2_approx(Bw0) - fmaf(cxq, cxq, cyq * cyq);
            const float r   = __fdividef(Bw1, Bw0);
            const int p = atomicAdd(&cntc, 1);
            if (p < CAPC) {
                shC[p]  = make_float4(ax, 2.0f * cyq, cc, r);
                shCs[p] = ex2_approx(ax * DQ);
            }
        } else {
            const float m0 = -HALF_LOG2E * __fdividef(M2, fmaxf(s0 * qk, M2));
            const float m1 = -HALF_LOG2E * __fdividef(M2, fmaxf(s1 * qk, M2));
            const int p = atomicAdd(&cntg, 1);
            if (p < CAPG) {
                shG[p]  = make_float4(cxs, cys, m0, m1);
                shGb[p] = make_float2(Bw0, Bw1);
            }
        }
    }
    __syncthreads();

    // ---- Phase 2: 64 pixel-pairs x 4-way survivor split ----
    const int grp = tid >> 6;                // survivor group 0..3
    const int pl  = tid & (NPAIR - 1);       // pixel-pair index
    const int w0  = tx0 + ((pl & 7) << 1);   // even column of the pair
    const int h   = ty0 + (pl >> 3);
    // Exact grid values for the even pixel (match reference coordinates);
    // odd pixel reached by the constant step factor sx.
    const float pxs = px[w0] * d2p;
    const float pys = py[h * IMG] * d2p;
    const float pxq = fmaf(pxs, SQRT_HL2E, -cpx);   // tile-centered q units
    const float pyq = fmaf(pys, SQRT_HL2E, -cpy);
    const float ppe = -fmaf(pxq, pxq, pyq * pyq);
    const float pxq1 = pxq + DQ;
    const float ppo = -fmaf(pxq1, pxq1, pyq * pyq);
    const float Ke  = ex2_approx(ppe);              // per-pixel factors
    const float Ko  = ex2_approx(ppo);

    const int nc = min(cntc, CAPC);
    const int ng = min(cntg, CAPG);
    const int c_lo = (nc * grp)       >> 2;
    const int c_hi = (nc * (grp + 1)) >> 2;
    const int g_lo = (ng * grp)       >> 2;
    const int g_hi = (ng * (grp + 1)) >> 2;

    float ac0e = 0.0f, ac1e = 0.0f, ac0o = 0.0f, ac1o = 0.0f;  // clamped (x K pending)
    float ag0e = 0.0f, ag1e = 0.0f, ag0o = 0.0f, ag1o = 0.0f;  // general

    // Clamped list: ONE EX2 serves both batches AND both pixels of the pair.
    #pragma unroll 4
    for (int i = c_lo; i < c_hi; i++) {
        const float4 a = shC[i];
        const float sx = shCs[i];
        const float v  = fmaf(a.x, pxq, fmaf(a.y, pyq, a.z));
        const float g0 = ex2_approx(v);          // even pixel (= Bw0*gauss/Ke)
        const float g1 = g0 * sx;                // odd pixel  (= Bw0*gauss/Ko)
        ac0e += g0;
        ac1e = fmaf(a.w, g0, ac1e);
        ac0o += g1;
        ac1o = fmaf(a.w, g1, ac1o);
    }

    // General list: incremental d^2 for the odd pixel; 4 EX2 per pair-iter.
    #pragma unroll 2
    for (int i = g_lo; i < g_hi; i++) {
        const float4 a  = shG[i];
        const float2 bw = shGb[i];
        const float dx  = pxs - a.x;
        const float dy  = pys - a.y;
        const float d20 = fmaf(dx, dx, dy * dy);
        const float d21 = fmaf(2.0f * PSTEP, dx, d20 + PSTEP2);
        ag0e = fmaf(bw.x, ex2_approx(d20 * a.z), ag0e);
        ag1e = fmaf(bw.y, ex2_approx(d20 * a.w), ag1e);
        ag0o = fmaf(bw.x, ex2_approx(d21 * a.z), ag0o);
        ag1o = fmaf(bw.y, ex2_approx(d21 * a.w), ag1o);
    }

    const float p0e = fmaf(Ke, ac0e, ag0e);
    const float p1e = fmaf(Ke, ac1e, ag1e);
    const float p0o = fmaf(Ko, ac0o, ag0o);
    const float p1o = fmaf(Ko, ac1o, ag1o);

    if (grp != 0) red[grp - 1][pl] = make_float4(p0e, p1e, p0o, p1o);
    __syncthreads();

    if (grp == 0) {
        const float4 r0 = red[0][pl];
        const float4 r1 = red[1][pl];
        const float4 r2 = red[2][pl];
        const int pix = h * IMG + w0;
        const float2 o0 = make_float2(fminf((p0e + r0.x) + (r1.x + r2.x), 1.0f),
                                      fminf((p0o + r0.z) + (r1.z + r2.z), 1.0f));
        const float2 o1 = make_float2(fminf((p1e + r0.y) + (r1.y + r2.y), 1.0f),
                                      fminf((p1o + r0.w) + (r1.w + r2.w), 1.0f));
        *reinterpret_cast<float2*>(out + pix)        = o0;   // even index: aligned
        *reinterpret_cast<float2*>(out + NPIX + pix) = o1;
    }
}

extern "C" void kernel_launch(void* const* d_in, const int* in_sizes, int n_in,
                              void* d_out, int out_size)
{
    const float* stim = (const float*)d_in[0];   // [2,32,32]
    const float* vx   = (const float*)d_in[1];   // [1024]
    const float* vy   = (const float*)d_in[2];   // [1024]
    const float* M    = (const float*)d_in[3];   // [1024]
    const float* px   = (const float*)d_in[4];   // [256,256]
    const float* py   = (const float*)d_in[5];   // [256,256]
    const int*   idx  = (const int*)  d_in[6];   // [1024]
    float* out = (float*)d_out;                  // [2,1,256,256]

    fused_kernel<<<(IMG / TW) * (IMG / TH), 256>>>(stim, vx, vy, M, px, py, idx, out);
}